// round 5
// baseline (speedup 1.0000x reference)
#include <cuda_runtime.h>

#define BATCH 4096
#define NU    20
#define NCOL  120

// Output regions (floats): f1 | g1 | f2 | g2
#define F1OFF 0
#define G1OFF (BATCH * NU)
#define F2OFF (G1OFF + BATCH * NU * NCOL)
#define G2OFF (F2OFF + BATCH * NCOL)

// ---- shared memory float offsets ----
#define W1A  0        /* 48  */
#define B1A  48       /* 16  */
#define W2A  64       /* 48  */
#define B2A  112      /* 16  */
#define WB1T 128      /* 32 rows x stride 20 = 640, [n*20+k] */
#define BB1  768      /* 32  */
#define WB2T 800      /* 640 */
#define BB2  1440     /* 32  */
#define WC1T 1472     /* 16 rows x stride 36 = 576, [n*36+k] */
#define BC1  2048     /* 16  */
#define WC2T 2064     /* 576 */
#define BC2  2640     /* 16  */
#define WD1T 2656     /* 19 rows x stride 20 = 380, [n*20+k] */
#define BD1  3036     /* 19 (+1 pad) */
#define WD2T 3056     /* 186 rows x stride 20 = 3720 */
#define BD2  6776     /* 186 (+2 pad) */
#define SXH  6964     /* 2 rows x 24 (halo layout) */
#define HA   7012     /* 2 rows x 672 : [r*672 + mlp*336 + site*16+nn] */
#define HB   8356     /* 2 rows x 1280: [r*1280 + mlp*640 + site*32+nn] */
#define SMEM_FLOATS 10916

#define DOT16(acc, h4p, w0, w1, w2, w3)                              \
    {                                                                \
        float4 h0 = (h4p)[0], h1 = (h4p)[1], h2 = (h4p)[2], h3 = (h4p)[3]; \
        acc += h0.x*w0.x + h0.y*w0.y + h0.z*w0.z + h0.w*w0.w;        \
        acc += h1.x*w1.x + h1.y*w1.y + h1.z*w1.z + h1.w*w1.w;        \
        acc += h2.x*w2.x + h2.y*w2.y + h2.z*w2.z + h2.w*w2.w;        \
        acc += h3.x*w3.x + h3.y*w3.y + h3.z*w3.z + h3.w*w3.w;        \
    }

__global__ __launch_bounds__(256, 4) void CGN_fused_kernel(
    const float* __restrict__ x,
    const float* __restrict__ w1a, const float* __restrict__ bb1a,
    const float* __restrict__ w1b, const float* __restrict__ bb1b,
    const float* __restrict__ w1c, const float* __restrict__ bb1c,
    const float* __restrict__ w1d, const float* __restrict__ bb1d,
    const float* __restrict__ w2a, const float* __restrict__ bb2a,
    const float* __restrict__ w2b, const float* __restrict__ bb2b,
    const float* __restrict__ w2c, const float* __restrict__ bb2c,
    const float* __restrict__ w2d, const float* __restrict__ bb2d,
    float* __restrict__ out)
{
    __shared__ float sm[SMEM_FLOATS];
    const int tid = threadIdx.x;
    const int b   = blockIdx.x;        // handles batch rows 2b, 2b+1

    // ---- Phase Z: zero-fill g1 & g2 for both rows (pure STG.128) ----
    {
        const float4 z4 = make_float4(0.f, 0.f, 0.f, 0.f);
        #pragma unroll
        for (int r = 0; r < 2; r++) {
            int row = b * 2 + r;
            float4* p1 = reinterpret_cast<float4*>(out + G1OFF + (size_t)row * 2400);
            for (int q = tid; q < 600; q += 256) p1[q] = z4;
            float4* p2 = reinterpret_cast<float4*>(out + G2OFF + (size_t)row * 14400);
            for (int q = tid; q < 3600; q += 256) p2[q] = z4;
        }
    }

    // ---- stage weights (transposing b/c/d layers) + x rows (halo) ----
    #define CP(off, src, n) for (int i = tid; i < (n); i += 256) sm[(off) + i] = (src)[i];
    CP(W1A, w1a, 48)  CP(B1A, bb1a, 16)
    CP(W2A, w2a, 48)  CP(B2A, bb2a, 16)
    CP(BB1, bb1b, 32) CP(BB2, bb2b, 32)
    CP(BC1, bb1c, 16) CP(BC2, bb2c, 16)
    CP(BD1, bb1d, 19) CP(BD2, bb2d, 186)
    #undef CP
    for (int i = tid; i < 512; i += 256) {              // layer b: 16x32
        int n = i & 31, k = i >> 5;
        sm[WB1T + n * 20 + k] = w1b[i];
        sm[WB2T + n * 20 + k] = w2b[i];
    }
    for (int i = tid; i < 512; i += 256) {              // layer c: 32x16
        int n = i & 15, k = i >> 4;
        sm[WC1T + n * 36 + k] = w1c[i];
        sm[WC2T + n * 36 + k] = w2c[i];
    }
    for (int i = tid; i < 304; i += 256) {              // layer d1: 16x19
        int k = i / 19, n = i - k * 19;
        sm[WD1T + n * 20 + k] = w1d[i];
    }
    for (int i = tid; i < 2976; i += 256) {             // layer d2: 16x186
        int k = i / 186, n = i - k * 186;
        sm[WD2T + n * 20 + k] = w2d[i];
    }
    if (tid < 40) {                                     // x with halo
        int r = tid >= 20, s = tid - r * 20;
        float v = x[(size_t)(b * 2 + r) * NU + s];
        sm[SXH + r * 24 + 1 + s] = v;
        if (s == 19) sm[SXH + r * 24]      = v;
        if (s == 0)  sm[SXH + r * 24 + 21] = v;
    }
    __syncthreads();

    // ---- Phase A: layer a (3 -> 16), 2 mlps x 20 sites x 2 rows = 1280 tasks ----
    for (int t = tid; t < 1280; t += 256) {
        int r    = t >= 640;
        int rem  = t - r * 640;
        int site = rem >> 5;
        int n    = rem & 31;
        int sxb  = SXH + r * 24;
        float x0 = sm[sxb + site];
        float x1 = sm[sxb + site + 1];
        float x2 = sm[sxb + site + 2];
        bool m1 = n < 16;
        int  nn = n & 15;
        const float* W = m1 ? &sm[W1A] : &sm[W2A];
        float bias     = m1 ? sm[B1A + nn] : sm[B2A + nn];
        float acc = bias + x0 * W[nn] + x1 * W[16 + nn] + x2 * W[32 + nn];
        sm[HA + r * 672 + (m1 ? 0 : 336) + site * 16 + nn] = fmaxf(acc, 0.f);
    }
    __syncthreads();

    // ---- Phase B: layer b (16 -> 32). 256 tasks = 64 slots x 4 site-groups ----
    {
        int n  = tid & 63;
        int sg = tid >> 6;
        bool m1 = n < 32;
        int  nn = n & 31;
        const float4* wp = reinterpret_cast<const float4*>(&sm[(m1 ? WB1T : WB2T) + nn * 20]);
        float4 w0 = wp[0], w1 = wp[1], w2 = wp[2], w3 = wp[3];
        float bias = sm[(m1 ? BB1 : BB2) + nn];
        #pragma unroll
        for (int r = 0; r < 2; r++) {
            int hab = HA + r * 672  + (m1 ? 0 : 336);
            int hbb = HB + r * 1280 + (m1 ? 0 : 640);
            #pragma unroll
            for (int s5 = 0; s5 < 5; s5++) {
                int s = sg * 5 + s5;
                const float4* h4 = reinterpret_cast<const float4*>(&sm[hab + s * 16]);
                float acc = bias;
                DOT16(acc, h4, w0, w1, w2, w3);
                sm[hbb + s * 32 + nn] = fmaxf(acc, 0.f);
            }
        }
    }
    __syncthreads();

    // ---- Phase C: layer c (32 -> 16). 256 tasks = 32 slots x 8 siterow-groups ----
    {
        int n  = tid & 31;
        int sg = tid >> 5;
        bool m1 = n < 16;
        int  nn = n & 15;
        const float4* wp = reinterpret_cast<const float4*>(&sm[(m1 ? WC1T : WC2T) + nn * 36]);
        float4 w[8];
        #pragma unroll
        for (int i = 0; i < 8; i++) w[i] = wp[i];
        float bias = sm[(m1 ? BC1 : BC2) + nn];
        #pragma unroll
        for (int q = 0; q < 5; q++) {
            int sr = sg * 5 + q;            // 0..39
            int r  = sr >= 20;
            int s  = sr - r * 20;
            const float4* h4 = reinterpret_cast<const float4*>(
                &sm[HB + r * 1280 + (m1 ? 0 : 640) + s * 32]);
            float acc = bias;
            #pragma unroll
            for (int i = 0; i < 8; i++) {
                float4 h = h4[i];
                acc += h.x * w[i].x + h.y * w[i].y + h.z * w[i].z + h.w * w[i].w;
            }
            sm[HA + r * 672 + (m1 ? 0 : 336) + s * 16 + nn] = fmaxf(acc, 0.f);
        }
    }
    __syncthreads();

    // ---- Phase D: output layer fused with banded scatter.
    //      1025 groups = 205 neurons x 5 site-groups (4 sites x 2 rows each).
    //      Weight col = 4 LDS.128 from transposed smem; incremental col math. ----
    for (int g = tid; g < 1025; g += 256) {
        int nrn = g % 205;
        int sg  = g / 205;
        int s0  = sg * 4;
        bool is1 = nrn < 19;
        int m = nrn - 19;
        const float4* wp;
        float bias;
        if (is1) { wp = reinterpret_cast<const float4*>(&sm[WD1T + nrn * 20]); bias = sm[BD1 + nrn]; }
        else     { wp = reinterpret_cast<const float4*>(&sm[WD2T + m   * 20]); bias = sm[BD2 + m]; }
        float4 w0 = wp[0], w1 = wp[1], w2 = wp[2], w3 = wp[3];

        int cls, col0 = 0, zq = 0;
        if (is1) {
            if (nrn == 0) cls = 0;
            else {
                cls = 1;
                col0 = ((s0 + 19) % 20) * 6 + (nrn - 1);
                if (col0 >= 120) col0 -= 120;
            }
        } else if (m < 6) {
            cls = 2;
        } else {
            cls = 3;
            zq = (m - 6) / 30;
            int jq = (m - 6) - zq * 30;
            col0 = ((s0 + 18) % 20) * 6 + jq;
            if (col0 >= 120) col0 -= 120;
        }

        #pragma unroll
        for (int r = 0; r < 2; r++) {
            int row = b * 2 + r;
            int hcb = HA + r * 672 + (is1 ? 0 : 336);
            int col = col0;
            #pragma unroll
            for (int s5 = 0; s5 < 4; s5++) {
                int s = s0 + s5;
                const float4* h4 = reinterpret_cast<const float4*>(&sm[hcb + s * 16]);
                float acc = bias;
                DOT16(acc, h4, w0, w1, w2, w3);
                if (cls == 0) {
                    out[(size_t)row * NU + s] = acc;
                } else if (cls == 1) {
                    out[G1OFF + (size_t)row * 2400 + s * 120 + col] = acc;
                    col += 6; if (col >= 120) col -= 120;
                } else if (cls == 2) {
                    out[F2OFF + (size_t)row * NCOL + s * 6 + m] = acc;
                } else {
                    out[G2OFF + (size_t)row * 14400 + (s * 6 + zq) * 120 + col] = acc;
                    col += 6; if (col >= 120) col -= 120;
                }
            }
        }
    }
}

extern "C" void kernel_launch(void* const* d_in, const int* in_sizes, int n_in,
                              void* d_out, int out_size) {
    const float* x   = (const float*)d_in[0];
    const float* w1a = (const float*)d_in[1];
    const float* b1a = (const float*)d_in[2];
    const float* w1b = (const float*)d_in[3];
    const float* b1b = (const float*)d_in[4];
    const float* w1c = (const float*)d_in[5];
    const float* b1c = (const float*)d_in[6];
    const float* w1d = (const float*)d_in[7];
    const float* b1d = (const float*)d_in[8];
    const float* w2a = (const float*)d_in[9];
    const float* b2a = (const float*)d_in[10];
    const float* w2b = (const float*)d_in[11];
    const float* b2b = (const float*)d_in[12];
    const float* w2c = (const float*)d_in[13];
    const float* b2c = (const float*)d_in[14];
    const float* w2d = (const float*)d_in[15];
    const float* b2d = (const float*)d_in[16];

    CGN_fused_kernel<<<BATCH / 2, 256>>>(
        x, w1a, b1a, w1b, b1b, w1c, b1c, w1d, b1d,
        w2a, b2a, w2b, b2b, w2c, b2c, w2d, b2d,
        (float*)d_out);
}

// round 6
// speedup vs baseline: 1.2077x; 1.2077x over previous
#include <cuda_runtime.h>

#define BATCH 4096
#define NU    20
#define NCOL  120

// Output regions (floats): f1 | g1 | f2 | g2
#define F1OFF 0
#define G1OFF (BATCH * NU)
#define F2OFF (G1OFF + BATCH * NU * NCOL)
#define G2OFF (F2OFF + BATCH * NCOL)

// ---- scratch (transposed weights), filled by setup kernel ----
// SWBo: WB1t [n32][k16] stride 20 (640), WB2t (+640)           -> 1280
// SWCo: WC1dup [n16][k32 dup2] stride 68 (1088), WC2dup (+1088)-> 2176
// SWDo: WDt [nrn205][k16] stride 20 (rows 0..18 = mlp1, 19.. = mlp2) -> 4100
#define SWBo 0
#define SWCo 1280
#define SWDo 3456
#define SCR_FLOATS 7556         /* = 3456 + 205*20 ; multiple of 4 */

__device__ __align__(16) float g_scr[SCR_FLOATS];

// ---- shared memory layout (floats) ----
#define SWB  SWBo               /* scratch copied to sm[0..7556) */
#define SWC  SWCo
#define SWD  SWDo
#define W1A  7556
#define B1A  7604
#define W2A  7620
#define B2A  7668
#define BB1  7684
#define BB2  7716
#define BC1  7748
#define BC2  7764
#define BDU  7780               /* 205 unified d-biases (+3 pad) */
#define SX   7988               /* 20 (+4 pad) */
#define HA   8012               /* flat  [mlp][site][k16]   : 640 */
#define HBI  8652               /* pair  [mlp][sp][k32][2]  : 1280 */
#define HCI  9932               /* pair  [mlp][sp][k16][2]  : 640 */
#define SMEM_FLOATS 10572

#define PACK2(d, lo, hi) \
    asm("mov.b64 %0, {%1, %2};" : "=l"(d) : "f"(lo), "f"(hi))
#define UNPACK2(lo, hi, s) \
    asm("mov.b64 {%0, %1}, %2;" : "=f"(lo), "=f"(hi) : "l"(s))
#define FMA2(d, a, b, c) \
    asm("fma.rn.f32x2 %0, %1, %2, %3;" : "=l"(d) : "l"(a), "l"(b), "l"(c))

#define DOT16(acc, h4p, w0, w1, w2, w3)                                    \
    {                                                                      \
        float4 h0 = (h4p)[0], h1 = (h4p)[1], h2 = (h4p)[2], h3 = (h4p)[3]; \
        acc += h0.x*w0.x + h0.y*w0.y + h0.z*w0.z + h0.w*w0.w;              \
        acc += h1.x*w1.x + h1.y*w1.y + h1.z*w1.z + h1.w*w1.w;              \
        acc += h2.x*w2.x + h2.y*w2.y + h2.z*w2.z + h2.w*w2.w;              \
        acc += h3.x*w3.x + h3.y*w3.y + h3.z*w3.z + h3.w*w3.w;              \
    }

// ---- one-block setup: transpose weights into scratch ----
__global__ void CGN_setup_kernel(
    const float* __restrict__ w1b, const float* __restrict__ w2b,
    const float* __restrict__ w1c, const float* __restrict__ w2c,
    const float* __restrict__ w1d, const float* __restrict__ w2d)
{
    const int tid = threadIdx.x;
    for (int i = tid; i < 512; i += 256) {            // b: 16x32 -> [n][k] s20
        int n = i & 31, k = i >> 5;
        g_scr[SWBo + n * 20 + k]       = w1b[k * 32 + n];
        g_scr[SWBo + 640 + n * 20 + k] = w2b[k * 32 + n];
    }
    for (int i = tid; i < 512; i += 256) {            // c: 32x16 -> dup [n][k][2] s68
        int n = i & 15, k = i >> 4;
        float v1 = w1c[k * 16 + n], v2 = w2c[k * 16 + n];
        g_scr[SWCo + n * 68 + k * 2]            = v1;
        g_scr[SWCo + n * 68 + k * 2 + 1]        = v1;
        g_scr[SWCo + 1088 + n * 68 + k * 2]     = v2;
        g_scr[SWCo + 1088 + n * 68 + k * 2 + 1] = v2;
    }
    for (int i = tid; i < 304; i += 256) {            // d1: 16x19 -> [n][k] s20
        int k = i / 19, n = i - k * 19;
        g_scr[SWDo + n * 20 + k] = w1d[i];
    }
    for (int i = tid; i < 2976; i += 256) {           // d2: 16x186 -> [n][k] s20
        int k = i / 186, n = i - k * 186;
        g_scr[SWDo + 380 + n * 20 + k] = w2d[i];
    }
}

__global__ __launch_bounds__(256, 4) void CGN_fused_kernel(
    const float* __restrict__ x,
    const float* __restrict__ w1a, const float* __restrict__ bb1a,
    const float* __restrict__ bb1b, const float* __restrict__ bb1c,
    const float* __restrict__ bb1d,
    const float* __restrict__ w2a, const float* __restrict__ bb2a,
    const float* __restrict__ bb2b, const float* __restrict__ bb2c,
    const float* __restrict__ bb2d,
    float* __restrict__ out)
{
    __shared__ __align__(16) float sm[SMEM_FLOATS];
    const int tid = threadIdx.x;
    const int b   = blockIdx.x;

    float* g1o = out + G1OFF + (size_t)b * 2400;
    float* g2o = out + G2OFF + (size_t)b * 14400;

    // ---- Phase Z: zero-fill g1 & g2 (pure STG.128) ----
    {
        const float4 z4 = make_float4(0.f, 0.f, 0.f, 0.f);
        float4* p1 = reinterpret_cast<float4*>(g1o);
        for (int q = tid; q < 600; q += 256) p1[q] = z4;
        float4* p2 = reinterpret_cast<float4*>(g2o);
        for (int q = tid; q < 3600; q += 256) p2[q] = z4;
    }

    // ---- stage: scratch memcpy (aligned float4) + biases + a-weights + x ----
    {
        const float4* s4 = reinterpret_cast<const float4*>(g_scr);
        float4* d4 = reinterpret_cast<float4*>(sm);
        for (int i = tid; i < SCR_FLOATS / 4; i += 256) d4[i] = s4[i];
    }
    #define CP(off, src, n) for (int i = tid; i < (n); i += 256) sm[(off) + i] = (src)[i];
    CP(W1A, w1a, 48)  CP(B1A, bb1a, 16)
    CP(W2A, w2a, 48)  CP(B2A, bb2a, 16)
    CP(BB1, bb1b, 32) CP(BB2, bb2b, 32)
    CP(BC1, bb1c, 16) CP(BC2, bb2c, 16)
    #undef CP
    for (int i = tid; i < 205; i += 256)
        sm[BDU + i] = (i < 19) ? bb1d[i] : bb2d[i - 19];
    for (int i = tid; i < NU; i += 256) sm[SX + i] = x[(size_t)b * NU + i];
    __syncthreads();

    // ---- Phase A: layer a (3->16), 640 tasks, flat store ----
    for (int t = tid; t < 640; t += 256) {
        int site = t >> 5;
        int n    = t & 31;
        float x0 = sm[SX + (site + 19) % NU];
        float x1 = sm[SX + site];
        float x2 = sm[SX + (site + 1) % NU];
        bool m1 = n < 16;
        int  nn = n & 15;
        const float* W = m1 ? &sm[W1A] : &sm[W2A];
        float bias     = m1 ? sm[B1A + nn] : sm[B2A + nn];
        float acc = bias + x0 * W[nn] + x1 * W[16 + nn] + x2 * W[32 + nn];
        sm[HA + (m1 ? 0 : 320) + site * 16 + nn] = fmaxf(acc, 0.f);
    }
    __syncthreads();

    // ---- Phase B: layer b (16->32), 256 tasks, scalar FFMA,
    //      w col = 4 LDS.128 (stride 20), store site-pair interleaved ----
    {
        int n  = tid & 63;
        int sg = tid >> 6;
        bool m1 = n < 32;
        int  nn = n & 31;
        const float4* wp = reinterpret_cast<const float4*>(&sm[SWB + (m1 ? 0 : 640) + nn * 20]);
        float4 w0 = wp[0], w1 = wp[1], w2 = wp[2], w3 = wp[3];
        float bias = sm[(m1 ? BB1 : BB2) + nn];
        int hab = HA  + (m1 ? 0 : 320);
        int hbb = HBI + (m1 ? 0 : 640);
        #pragma unroll
        for (int s5 = 0; s5 < 5; s5++) {
            int s = sg * 5 + s5;
            const float4* h4 = reinterpret_cast<const float4*>(&sm[hab + s * 16]);
            float acc = bias;
            DOT16(acc, h4, w0, w1, w2, w3);
            sm[hbb + (s >> 1) * 64 + nn * 2 + (s & 1)] = fmaxf(acc, 0.f);
        }
    }
    __syncthreads();

    // ---- Phase C: layer c (32->16), paired f32x2. 320 tasks:
    //      (sp, mlp, nn16). dup w (stride 68) + interleaved h -> 32 FFMA2 ----
    for (int t = tid; t < 320; t += 256) {
        int nn = t & 15;
        int m  = (t >> 4) & 1;
        int sp = t >> 5;
        const ulonglong2* wd = reinterpret_cast<const ulonglong2*>(&sm[SWC + m * 1088 + nn * 68]);
        const ulonglong2* hd = reinterpret_cast<const ulonglong2*>(&sm[HBI + m * 640 + sp * 64]);
        float bias = sm[(m ? BC2 : BC1) + nn];
        unsigned long long acc2;
        PACK2(acc2, bias, bias);
        #pragma unroll
        for (int j = 0; j < 16; j++) {
            ulonglong2 wv = wd[j];
            ulonglong2 hv = hd[j];
            FMA2(acc2, wv.x, hv.x, acc2);
            FMA2(acc2, wv.y, hv.y, acc2);
        }
        float lo, hi;
        UNPACK2(lo, hi, acc2);
        sm[HCI + m * 320 + sp * 32 + nn * 2]     = fmaxf(lo, 0.f);
        sm[HCI + m * 320 + sp * 32 + nn * 2 + 1] = fmaxf(hi, 0.f);
    }
    __syncthreads();

    // ---- Phase D: output layer + banded scatter, paired f32x2.
    //      1025 groups = 205 neurons x 5 site-groups (2 pairs = 4 sites). ----
    for (int g = tid; g < 1025; g += 256) {
        int nrn = g % 205;
        int sg  = g / 205;
        int s0  = sg * 4;
        bool is1 = nrn < 19;
        int m = nrn - 19;

        const float4* wp = reinterpret_cast<const float4*>(&sm[SWD + nrn * 20]);
        float4 wa = wp[0], wb = wp[1], wc = wp[2], wdd = wp[3];
        float wf[16] = { wa.x, wa.y, wa.z, wa.w,  wb.x, wb.y, wb.z, wb.w,
                         wc.x, wc.y, wc.z, wc.w,  wdd.x, wdd.y, wdd.z, wdd.w };
        unsigned long long w2[16], bias2;
        #pragma unroll
        for (int k = 0; k < 16; k++) PACK2(w2[k], wf[k], wf[k]);
        float bias = sm[BDU + nrn];
        PACK2(bias2, bias, bias);

        int cls, zq = 0, col = 0;
        if (is1) {
            if (nrn == 0) cls = 0;
            else {
                cls = 1;
                col = ((s0 + 19) % 20) * 6 + (nrn - 1);
                if (col >= 120) col -= 120;
            }
        } else if (m < 6) {
            cls = 2;
        } else {
            cls = 3;
            zq = (m - 6) / 30;
            int jq = (m - 6) - zq * 30;
            col = ((s0 + 18) % 20) * 6 + jq;
            if (col >= 120) col -= 120;
        }

        int hcb = HCI + (is1 ? 0 : 320);
        #pragma unroll
        for (int pp = 0; pp < 2; pp++) {
            int p = sg * 2 + pp;
            const ulonglong2* hd = reinterpret_cast<const ulonglong2*>(&sm[hcb + p * 32]);
            unsigned long long acc2 = bias2;
            #pragma unroll
            for (int j = 0; j < 8; j++) {
                ulonglong2 hv = hd[j];
                FMA2(acc2, w2[2 * j],     hv.x, acc2);
                FMA2(acc2, w2[2 * j + 1], hv.y, acc2);
            }
            float aA, aB;
            UNPACK2(aA, aB, acc2);
            int s = 2 * p;
            if (cls == 0) {
                out[(size_t)b * NU + s]     = aA;
                out[(size_t)b * NU + s + 1] = aB;
            } else if (cls == 1) {
                g1o[s * 120 + col] = aA;       col += 6; if (col >= 120) col -= 120;
                g1o[(s + 1) * 120 + col] = aB; col += 6; if (col >= 120) col -= 120;
            } else if (cls == 2) {
                out[F2OFF + (size_t)b * NCOL + s * 6 + m]       = aA;
                out[F2OFF + (size_t)b * NCOL + (s + 1) * 6 + m] = aB;
            } else {
                g2o[(s * 6 + zq) * 120 + col] = aA;       col += 6; if (col >= 120) col -= 120;
                g2o[((s + 1) * 6 + zq) * 120 + col] = aB; col += 6; if (col >= 120) col -= 120;
            }
        }
    }
}

extern "C" void kernel_launch(void* const* d_in, const int* in_sizes, int n_in,
                              void* d_out, int out_size) {
    const float* x   = (const float*)d_in[0];
    const float* w1a = (const float*)d_in[1];
    const float* b1a = (const float*)d_in[2];
    const float* w1b = (const float*)d_in[3];
    const float* b1b = (const float*)d_in[4];
    const float* w1c = (const float*)d_in[5];
    const float* b1c = (const float*)d_in[6];
    const float* w1d = (const float*)d_in[7];
    const float* b1d = (const float*)d_in[8];
    const float* w2a = (const float*)d_in[9];
    const float* b2a = (const float*)d_in[10];
    const float* w2b = (const float*)d_in[11];
    const float* b2b = (const float*)d_in[12];
    const float* w2c = (const float*)d_in[13];
    const float* b2c = (const float*)d_in[14];
    const float* w2d = (const float*)d_in[15];
    const float* b2d = (const float*)d_in[16];

    CGN_setup_kernel<<<1, 256>>>(w1b, w2b, w1c, w2c, w1d, w2d);
    CGN_fused_kernel<<<BATCH, 256>>>(
        x, w1a, b1a, b1b, b1c, b1d,
        w2a, b2a, b2b, b2c, b2d,
        (float*)d_out);
}